// round 7
// baseline (speedup 1.0000x reference)
#include <cuda_runtime.h>
#include <cuda_bf16.h>

#define NT 2000
#define NS 2048
#define NH 16
#define HPT 4   // heads per thread
#define PF 16   // prefetch depth; NT = 125*16

__device__ __forceinline__ float sigmoidf_(float x) {
    return 1.0f / (1.0f + expf(-x));
}

struct Ring { float p[PF], t[PF], e[PF]; };

__global__ __launch_bounds__(64, 1)
void waternet_kernel(const float* __restrict__ P, const float* __restrict__ T,
                     const float* __restrict__ E,
                     const float* __restrict__ w_o, const float* __restrict__ wF,
                     const float* __restrict__ wG, const float* __restrict__ wl,
                     const float* __restrict__ we, const float* __restrict__ wk,
                     const float* __restrict__ ws,
                     float* __restrict__ Qo, float* __restrict__ Fo,
                     float* __restrict__ Ho, float* __restrict__ Go)
{
    const unsigned t  = blockIdx.x * blockDim.x + threadIdx.x;  // 0..8191
    const unsigned s  = t >> 2;          // site (0..2047)
    const unsigned hq = t & 3;           // head quad (0..3)
    const unsigned h0 = hq * HPT;        // first head of this thread

    // ---- per-head constants (4 heads) ----
    float ssum = 0.0f;
    #pragma unroll
    for (int i = 0; i < NH; i++) ssum += expf(w_o[i]);
    float a[HPT], melt[HPT], cap[HPT], swe[HPT], swk[HPT], sws[HPT], swg[HPT];
    #pragma unroll
    for (int i = 0; i < HPT; i++) {
        const unsigned h = h0 + i;
        a[i]    = expf(w_o[h]) / ssum;
        melt[i] = expf(wF[h]) + 1.0f;
        cap[i]  = expf(2.0f * wl[h]);
        swe[i]  = sigmoidf_(we[h]);
        swk[i]  = sigmoidf_(wk[h]);
        sws[i]  = sigmoidf_(ws[h]);
        swg[i]  = sigmoidf_(wG[h]);
    }

    // ---- carries (4 heads each) ----
    float f[HPT] = {0,0,0,0}, hs[HPT] = {0,0,0,0}, g[HPT] = {0,0,0,0};

    // ---- deep prefetch ring (per-site, shared by the 4 heads) ----
    Ring r;
    #pragma unroll
    for (int i = 0; i < PF; i++) {
        const unsigned idx = (unsigned)i * NS + s;
        r.p[i] = __ldg(P + idx);
        r.t[i] = __ldg(T + idx);
        r.e[i] = __ldg(E + idx);
    }

    const unsigned out_stride = NS * NH;              // 32768
    unsigned oidx = s * NH + h0;                      // float4-aligned
    unsigned qidx = s;
    unsigned lidx = (unsigned)PF * NS + s;

    for (int k0 = 0; k0 < NT; k0 += PF) {
        const bool refill = (k0 + PF < NT);
        #pragma unroll
        for (int j = 0; j < PF; j++) {
            const float Pk = r.p[j], Tk = r.t[j], Ek = r.e[j];
            if (refill) {
                r.p[j] = __ldg(P + lidx);
                r.t[j] = __ldg(T + lidx);
                r.e[j] = __ldg(E + lidx);
                lidx += NS;
            }

            const float relT  = fmaxf(Tk, 0.0f);
            const float pcold = (Tk < 0.0f) ? Pk : 0.0f;
            const float pwarm = (Tk > 0.0f) ? Pk : 0.0f;

            float acc = 0.0f;
            float fv[HPT], hv[HPT], gv[HPT];
            #pragma unroll
            for (int i = 0; i < HPT; i++) {
                // SnowBucket
                const float sm = relT * melt[i];
                const float m  = fminf(sm, f[i]);
                f[i] = (f[i] - m) + pcold;
                const float x = pwarm + m;
                // SoilBucket
                const float hn = hs[i] + x;
                const float h1 = fmaxf(hn - cap[i], 0.0f);
                const float q1 = fmaxf(h1 - Ek * swe[i], 0.0f);
                const float h2 = fminf(hn, cap[i]);
                const float q2 = h2 * swk[i];
                hs[i] = h2 - q2;
                const float q2a = q2 * sws[i];
                const float q2b = q2 - q2a;
                // LinearBucket
                const float gn = g[i] + q2b;
                const float q3 = gn * swg[i];
                g[i] = gn - q3;

                fv[i] = f[i]; hv[i] = hs[i]; gv[i] = g[i];
                acc = fmaf(q1 + q2a + q3, a[i], acc);
            }

            // vector stores: 4 heads = 16B, aligned
            __stcs((float4*)(Fo + oidx), make_float4(fv[0], fv[1], fv[2], fv[3]));
            __stcs((float4*)(Ho + oidx), make_float4(hv[0], hv[1], hv[2], hv[3]));
            __stcs((float4*)(Go + oidx), make_float4(gv[0], gv[1], gv[2], gv[3]));
            oidx += out_stride;

            // Q: sum the 4 thread-partials within the 4-lane site group
            acc += __shfl_xor_sync(0xffffffffu, acc, 2);
            acc += __shfl_xor_sync(0xffffffffu, acc, 1);
            if (hq == 0) __stcs(Qo + qidx, acc);
            qidx += NS;
        }
    }
}

extern "C" void kernel_launch(void* const* d_in, const int* in_sizes, int n_in,
                              void* d_out, int out_size) {
    const float* big[3]    = {nullptr, nullptr, nullptr};
    const float* small7[7] = {nullptr, nullptr, nullptr, nullptr, nullptr, nullptr, nullptr};
    int nb = 0, nsml = 0;
    for (int i = 0; i < n_in; i++) {
        if (d_in[i] == nullptr) continue;
        if (in_sizes[i] > 10000) {
            if (nb < 3) big[nb++] = (const float*)d_in[i];
        } else if (in_sizes[i] > 0) {
            if (nsml < 7) small7[nsml++] = (const float*)d_in[i];
        }
    }
    if (nb < 3 || nsml < 7) return;

    const float* P   = big[0];
    const float* T   = big[1];
    const float* E   = big[2];
    const float* w_o = small7[0];
    const float* wF  = small7[1];
    const float* wG  = small7[2];
    const float* wl  = small7[3];
    const float* we  = small7[4];
    const float* wk  = small7[5];
    const float* ws  = small7[6];

    float* out = (float*)d_out;
    const long long QN = (long long)NT * NS;
    float* Qo = out;
    float* Fo = Qo + QN;
    float* Ho = Fo + QN * NH;
    float* Go = Ho + QN * NH;

    // 8192 threads = NS * NH / HPT; 128 blocks x 64 threads, one block per SM.
    const int threads = 64;
    const int blocks  = (NS * (NH / HPT)) / threads;  // 128
    waternet_kernel<<<blocks, threads>>>(P, T, E, w_o, wF, wG, wl, we, wk, ws,
                                         Qo, Fo, Ho, Go);
}

// round 8
// speedup vs baseline: 1.0176x; 1.0176x over previous
#include <cuda_runtime.h>
#include <cuda_bf16.h>

#define NT 2000
#define NS 2048
#define NH 16
#define HPT 2   // heads per thread
#define PF 16   // prefetch depth; NT = 125*16

__device__ __forceinline__ float sigmoidf_(float x) {
    return 1.0f / (1.0f + expf(-x));
}

struct Ring { float p[PF], t[PF], e[PF]; };

__global__ __launch_bounds__(128, 1)
void waternet_kernel(const float* __restrict__ P, const float* __restrict__ T,
                     const float* __restrict__ E,
                     const float* __restrict__ w_o, const float* __restrict__ wF,
                     const float* __restrict__ wG, const float* __restrict__ wl,
                     const float* __restrict__ we, const float* __restrict__ wk,
                     const float* __restrict__ ws,
                     float* __restrict__ Qo, float* __restrict__ Fo,
                     float* __restrict__ Ho, float* __restrict__ Go)
{
    const unsigned t  = blockIdx.x * blockDim.x + threadIdx.x;  // 0..16383
    const unsigned s  = t >> 3;          // site (0..2047), 8 pair-threads per site
    const unsigned hp = t & 7;           // head-pair index (0..7)
    const unsigned h0 = hp * HPT;        // first head of this thread

    // ---- per-head constants (2 heads) ----
    float ssum = 0.0f;
    #pragma unroll
    for (int i = 0; i < NH; i++) ssum += expf(w_o[i]);
    float a[HPT], melt[HPT], cap[HPT], swe[HPT], swk[HPT], sws[HPT], swg[HPT];
    #pragma unroll
    for (int i = 0; i < HPT; i++) {
        const unsigned h = h0 + i;
        a[i]    = expf(w_o[h]) / ssum;
        melt[i] = expf(wF[h]) + 1.0f;
        cap[i]  = expf(2.0f * wl[h]);
        swe[i]  = sigmoidf_(we[h]);
        swk[i]  = sigmoidf_(wk[h]);
        sws[i]  = sigmoidf_(ws[h]);
        swg[i]  = sigmoidf_(wG[h]);
    }

    // ---- carries ----
    float f[HPT] = {0,0}, hs[HPT] = {0,0}, g[HPT] = {0,0};

    // ---- deep prefetch ring (per-site, broadcast across the 8 pair-lanes) ----
    Ring r;
    #pragma unroll
    for (int i = 0; i < PF; i++) {
        const unsigned idx = (unsigned)i * NS + s;
        r.p[i] = __ldg(P + idx);
        r.t[i] = __ldg(T + idx);
        r.e[i] = __ldg(E + idx);
    }

    const unsigned out_stride = NS * NH;              // 32768
    unsigned oidx = s * NH + h0;                      // float2-aligned (h0 even)
    unsigned qidx = s;
    unsigned lidx = (unsigned)PF * NS + s;

    for (int k0 = 0; k0 < NT; k0 += PF) {
        const bool refill = (k0 + PF < NT);
        #pragma unroll
        for (int j = 0; j < PF; j++) {
            const float Pk = r.p[j], Tk = r.t[j], Ek = r.e[j];
            if (refill) {
                r.p[j] = __ldg(P + lidx);
                r.t[j] = __ldg(T + lidx);
                r.e[j] = __ldg(E + lidx);
                lidx += NS;
            }

            const float relT  = fmaxf(Tk, 0.0f);
            const float pcold = (Tk < 0.0f) ? Pk : 0.0f;
            const float pwarm = (Tk > 0.0f) ? Pk : 0.0f;

            float acc = 0.0f;
            #pragma unroll
            for (int i = 0; i < HPT; i++) {
                // SnowBucket
                const float sm = relT * melt[i];
                const float m  = fminf(sm, f[i]);
                f[i] = (f[i] - m) + pcold;
                const float x = pwarm + m;
                // SoilBucket  (h2 = hn - relu(hn-cap) == min(hn, cap))
                const float hn = hs[i] + x;
                const float h1 = fmaxf(hn - cap[i], 0.0f);
                const float q1 = fmaxf(h1 - Ek * swe[i], 0.0f);
                const float h2 = fminf(hn, cap[i]);
                const float q2 = h2 * swk[i];
                hs[i] = h2 - q2;
                const float q2a = q2 * sws[i];
                const float q2b = q2 - q2a;
                // LinearBucket
                const float gn = g[i] + q2b;
                const float q3 = gn * swg[i];
                g[i] = gn - q3;

                acc = fmaf(q1 + q2a + q3, a[i], acc);
            }

            // vector stores: 2 heads = 8B aligned; warp covers 4 sites x 64B = 256B
            __stcs((float2*)(Fo + oidx), make_float2(f[0],  f[1]));
            __stcs((float2*)(Ho + oidx), make_float2(hs[0], hs[1]));
            __stcs((float2*)(Go + oidx), make_float2(g[0],  g[1]));
            oidx += out_stride;

            // Q: butterfly over the 8-lane site group (each lane holds 2-head partial)
            acc += __shfl_xor_sync(0xffffffffu, acc, 4);
            acc += __shfl_xor_sync(0xffffffffu, acc, 2);
            acc += __shfl_xor_sync(0xffffffffu, acc, 1);
            if (hp == 0) __stcs(Qo + qidx, acc);   // 4 lanes/warp, consecutive sites
            qidx += NS;
        }
    }
}

extern "C" void kernel_launch(void* const* d_in, const int* in_sizes, int n_in,
                              void* d_out, int out_size) {
    const float* big[3]    = {nullptr, nullptr, nullptr};
    const float* small7[7] = {nullptr, nullptr, nullptr, nullptr, nullptr, nullptr, nullptr};
    int nb = 0, nsml = 0;
    for (int i = 0; i < n_in; i++) {
        if (d_in[i] == nullptr) continue;
        if (in_sizes[i] > 10000) {
            if (nb < 3) big[nb++] = (const float*)d_in[i];
        } else if (in_sizes[i] > 0) {
            if (nsml < 7) small7[nsml++] = (const float*)d_in[i];
        }
    }
    if (nb < 3 || nsml < 7) return;

    const float* P   = big[0];
    const float* T   = big[1];
    const float* E   = big[2];
    const float* w_o = small7[0];
    const float* wF  = small7[1];
    const float* wG  = small7[2];
    const float* wl  = small7[3];
    const float* we  = small7[4];
    const float* wk  = small7[5];
    const float* ws  = small7[6];

    float* out = (float*)d_out;
    const long long QN = (long long)NT * NS;
    float* Qo = out;
    float* Fo = Qo + QN;
    float* Ho = Fo + QN * NH;
    float* Go = Ho + QN * NH;

    // 16384 threads: 128 blocks x 128 threads -> 4 warps/SM, one per SMSP.
    const int threads = 128;
    const int blocks  = (NS * (NH / HPT)) / threads;  // 128
    waternet_kernel<<<blocks, threads>>>(P, T, E, w_o, wF, wG, wl, we, wk, ws,
                                         Qo, Fo, Ho, Go);
}

// round 9
// speedup vs baseline: 1.6319x; 1.6037x over previous
#include <cuda_runtime.h>
#include <cuda_bf16.h>

#define NT     2000
#define NS     2048
#define NH     16
#define CHUNK  16            // steps per chunk; NT = 125*16
#define NCHUNK (NT / CHUNK)  // 125
#define SPB    16            // sites per block
#define THREADS 256          // SPB * NH
#define WARPS   8
#define QPAD    36           // padded row stride for qsm (16B-aligned, low conflicts)

__device__ __forceinline__ float sigmoidf_(float x) {
    return 1.0f / (1.0f + expf(-x));
}

__global__ __launch_bounds__(THREADS, 1)
void waternet_kernel(const float* __restrict__ P, const float* __restrict__ T,
                     const float* __restrict__ E,
                     const float* __restrict__ w_o, const float* __restrict__ wF,
                     const float* __restrict__ wG, const float* __restrict__ wl,
                     const float* __restrict__ we, const float* __restrict__ wk,
                     const float* __restrict__ ws,
                     float* __restrict__ Qo, float* __restrict__ Fo,
                     float* __restrict__ Ho, float* __restrict__ Go)
{
    __shared__ __align__(16) float tile[2][3][CHUNK][SPB];  // forcings, double-buffered
    __shared__ __align__(16) float qsm[WARPS][CHUNK][QPAD]; // per-warp Q staging

    const unsigned tid  = threadIdx.x;
    const unsigned warp = tid >> 5;
    const unsigned lane = tid & 31;
    const unsigned sl   = tid >> 4;          // local site 0..15
    const unsigned h    = tid & 15;          // head
    const unsigned s0   = blockIdx.x * SPB;  // block's first site
    const unsigned s    = s0 + sl;

    // tile-loader role: thread u loads step (u>>4), local site (u&15)
    const unsigned ljj = tid >> 4;
    const unsigned lss = tid & 15;
    const unsigned lbase0 = ljj * NS + s0 + lss;

    // ---- per-head constants ----
    float ssum = 0.0f;
    #pragma unroll
    for (int i = 0; i < NH; i++) ssum += expf(w_o[i]);
    const float a    = expf(w_o[h]) / ssum;
    const float melt = expf(wF[h]) + 1.0f;
    const float cap  = expf(2.0f * wl[h]);
    const float swe  = sigmoidf_(we[h]);
    const float swk  = sigmoidf_(wk[h]);
    const float sws  = sigmoidf_(ws[h]);
    const float swg  = sigmoidf_(wG[h]);

    float f = 0.0f, hs = 0.0f, g = 0.0f;

    // load chunk 0 into buffer 0
    tile[0][0][ljj][lss] = __ldg(P + lbase0);
    tile[0][1][ljj][lss] = __ldg(T + lbase0);
    tile[0][2][ljj][lss] = __ldg(E + lbase0);
    __syncthreads();

    unsigned oidx = s * NH + h;
    const unsigned out_stride = NS * NH;

    for (int c = 0; c < NCHUNK; c++) {
        const int rd = c & 1;

        // prefetch next chunk into registers (covered by this chunk's compute)
        float rp = 0.0f, rt = 0.0f, re = 0.0f;
        if (c < NCHUNK - 1) {
            const unsigned base = (unsigned)(c + 1) * CHUNK * NS + lbase0;
            rp = __ldg(P + base);
            rt = __ldg(T + base);
            re = __ldg(E + base);
        }

        #pragma unroll
        for (int j = 0; j < CHUNK; j++) {
            const float Pk = tile[rd][0][j][sl];
            const float Tk = tile[rd][1][j][sl];
            const float Ek = tile[rd][2][j][sl];

            // SnowBucket
            const float sm    = fmaxf(Tk, 0.0f) * melt;
            const float pcold = (Tk < 0.0f) ? Pk : 0.0f;
            const float pwarm = (Tk > 0.0f) ? Pk : 0.0f;
            const float m     = fminf(sm, f);
            f = (f - m) + pcold;
            const float x = pwarm + m;

            // SoilBucket (h2 = hn - relu(hn-cap) == min(hn, cap))
            const float hn = hs + x;
            const float h1 = fmaxf(hn - cap, 0.0f);
            const float q1 = fmaxf(h1 - Ek * swe, 0.0f);
            const float h2 = fminf(hn, cap);
            const float q2 = h2 * swk;
            hs = h2 - q2;
            const float q2a = q2 * sws;
            const float q2b = q2 - q2a;

            // LinearBucket
            const float gn = g + q2b;
            const float q3 = gn * swg;
            g = gn - q3;

            // coalesced streaming state stores (128B per warp per array)
            __stcs(Fo + oidx, f);
            __stcs(Ho + oidx, hs);
            __stcs(Go + oidx, g);
            oidx += out_stride;

            // stage this head's Q contribution (reduced once per chunk)
            qsm[warp][j][lane] = (q1 + q2a + q3) * a;
        }

        __syncwarp();
        // per-warp Q reduction: lane -> (local site d, step j); sums 16 heads
        {
            const unsigned d = lane >> 4;
            const unsigned j = lane & 15;
            const float4* q4 = (const float4*)&qsm[warp][j][d * 16];
            const float4 v0 = q4[0], v1 = q4[1], v2 = q4[2], v3 = q4[3];
            const float sum = (((v0.x + v0.y) + (v0.z + v0.w)) +
                               ((v1.x + v1.y) + (v1.z + v1.w))) +
                              (((v2.x + v2.y) + (v2.z + v2.w)) +
                               ((v3.x + v3.y) + (v3.z + v3.w)));
            const unsigned qi = (unsigned)(c * CHUNK + j) * NS + s0 + warp * 2 + d;
            __stcs(Qo + qi, sum);
        }
        __syncwarp();

        // publish prefetched chunk into the other buffer
        if (c < NCHUNK - 1) {
            tile[rd ^ 1][0][ljj][lss] = rp;
            tile[rd ^ 1][1][ljj][lss] = rt;
            tile[rd ^ 1][2][ljj][lss] = re;
        }
        __syncthreads();
    }
}

extern "C" void kernel_launch(void* const* d_in, const int* in_sizes, int n_in,
                              void* d_out, int out_size) {
    const float* big[3]    = {nullptr, nullptr, nullptr};
    const float* small7[7] = {nullptr, nullptr, nullptr, nullptr, nullptr, nullptr, nullptr};
    int nb = 0, nsml = 0;
    for (int i = 0; i < n_in; i++) {
        if (d_in[i] == nullptr) continue;
        if (in_sizes[i] > 10000) {
            if (nb < 3) big[nb++] = (const float*)d_in[i];
        } else if (in_sizes[i] > 0) {
            if (nsml < 7) small7[nsml++] = (const float*)d_in[i];
        }
    }
    if (nb < 3 || nsml < 7) return;

    const float* P   = big[0];
    const float* T   = big[1];
    const float* E   = big[2];
    const float* w_o = small7[0];
    const float* wF  = small7[1];
    const float* wG  = small7[2];
    const float* wl  = small7[3];
    const float* we  = small7[4];
    const float* wk  = small7[5];
    const float* ws  = small7[6];

    float* out = (float*)d_out;
    const long long QN = (long long)NT * NS;
    float* Qo = out;
    float* Fo = Qo + QN;
    float* Ho = Fo + QN * NH;
    float* Go = Ho + QN * NH;

    // 128 blocks x 256 threads = 32768 threads exactly; 8 warps/SM (2 per SMSP).
    const int blocks = NS / SPB;  // 128
    waternet_kernel<<<blocks, THREADS>>>(P, T, E, w_o, wF, wG, wl, we, wk, ws,
                                         Qo, Fo, Ho, Go);
}